// round 1
// baseline (speedup 1.0000x reference)
#include <cuda_runtime.h>

// GroupEmbedding: out[b,g,d] = sum_f x[b, g*8+f] * W[g,f,d] + bias[g,d],
// zeroed where masked_group_idx[b] == g.
// B=8192, NF=128, G=16, F=8, D=512. Output 256MB fp32 -> HBM-write-bound.

#define B_DIM  8192
#define NF_DIM 128
#define G_DIM  16
#define F_DIM  8
#define D_DIM  512
#define TB     64    // b-values per block

// Flag: is masked_group_idx stored as int64 (1) or int32 (0)?
__device__ int g_is64;

__global__ void detect_idx_kernel(const int* __restrict__ mg) {
    // Interpret the first 64 logical int64 elements as int32 pairs.
    // int64 data: high word == 0, low word in [0,16). int32 data: the "high"
    // word is itself a random value in [0,16), nonzero w.p. 15/16 per slot.
    int ok = 1;
    #pragma unroll 1
    for (int i = 0; i < 64; ++i) {
        int lo = mg[2 * i];
        int hi = mg[2 * i + 1];
        if (hi != 0 || ((unsigned)lo) >= 16u) { ok = 0; break; }
    }
    g_is64 = ok;
}

__device__ __forceinline__ unsigned long long fma2(unsigned long long a,
                                                   unsigned long long b,
                                                   unsigned long long c) {
    unsigned long long d;
    asm("fma.rn.f32x2 %0, %1, %2, %3;" : "=l"(d) : "l"(a), "l"(b), "l"(c));
    return d;
}

__device__ __forceinline__ unsigned long long pack2(float x) {
    unsigned long long r;
    asm("mov.b64 %0, {%1, %1};" : "=l"(r) : "r"(__float_as_uint(x)));
    return r;
}

union F4U {
    float4 v;
    struct { unsigned long long lo, hi; } u;
};

__global__ __launch_bounds__(128) void ge_kernel(
    const float* __restrict__ x, const float* __restrict__ W,
    const float* __restrict__ bias, const int* __restrict__ mg,
    float* __restrict__ out)
{
    const int g  = blockIdx.y;
    const int d4 = threadIdx.x;            // 0..127, owns out[.., g, 4*d4 .. 4*d4+3]
    const int b0 = blockIdx.x * TB;
    const int is64 = g_is64;

    // Preload W[g, :, 4*d4 .. 4*d4+3] (8 x float4 = 32 regs) and bias.
    F4U w[F_DIM];
    #pragma unroll
    for (int f = 0; f < F_DIM; ++f)
        w[f].v = *reinterpret_cast<const float4*>(W + (size_t)(g * F_DIM + f) * D_DIM + d4 * 4);
    F4U bb;
    bb.v = *reinterpret_cast<const float4*>(bias + (size_t)g * D_DIM + d4 * 4);

    // x[b, g*8 .. g*8+7] as two float4 (32B aligned).
    const float4* xp = reinterpret_cast<const float4*>(x) + (size_t)b0 * (NF_DIM / 4) + g * 2;

    // Software pipeline: prime first iteration's loads.
    float4 xa = __ldg(xp);
    float4 xb = __ldg(xp + 1);
    int    m  = is64 ? mg[2 * b0] : mg[b0];

    #pragma unroll 1
    for (int t = 0; t < TB; ++t) {
        const int b = b0 + t;

        float4 nxa = xa, nxb = xb; int nm = 0;
        if (t + 1 < TB) {
            const float4* nxp = xp + (size_t)(t + 1) * (NF_DIM / 4);
            nxa = __ldg(nxp);
            nxb = __ldg(nxp + 1);
            nm  = is64 ? mg[2 * (b + 1)] : mg[b + 1];
        }

        F4U acc;
        acc.u.lo = bb.u.lo;
        acc.u.hi = bb.u.hi;
        const float xf[F_DIM] = {xa.x, xa.y, xa.z, xa.w, xb.x, xb.y, xb.z, xb.w};
        #pragma unroll
        for (int f = 0; f < F_DIM; ++f) {
            unsigned long long xs = pack2(xf[f]);
            acc.u.lo = fma2(xs, w[f].u.lo, acc.u.lo);   // d pair (0,1)
            acc.u.hi = fma2(xs, w[f].u.hi, acc.u.hi);   // d pair (2,3)
        }

        if (m == g) acc.v = make_float4(0.f, 0.f, 0.f, 0.f);

        // Streaming store: output (256MB) is write-once, don't thrash L2.
        __stcs(reinterpret_cast<float4*>(out + ((size_t)b * G_DIM + g) * D_DIM + d4 * 4), acc.v);

        xa = nxa; xb = nxb; m = nm;
    }
}

extern "C" void kernel_launch(void* const* d_in, const int* in_sizes, int n_in,
                              void* d_out, int out_size) {
    const float* x    = (const float*)d_in[0];
    const float* W    = (const float*)d_in[1];
    const float* bias = (const float*)d_in[2];
    // d_in[3] = group_idx: identity arange(G*F).reshape(G,F) -> ignored.
    const int*   mg   = (const int*)d_in[4];
    float*       out  = (float*)d_out;

    detect_idx_kernel<<<1, 1>>>(mg);

    dim3 grid(B_DIM / TB, G_DIM);
    ge_kernel<<<grid, 128>>>(x, W, bias, mg, out);
}

// round 2
// speedup vs baseline: 1.0741x; 1.0741x over previous
#include <cuda_runtime.h>

// GroupEmbedding: out[b,g,d] = sum_f x[b, g*8+f] * W[g,f,d] + bias[g,d],
// zeroed where masked_group_idx[b] == g.
// B=8192, NF=128, G=16, F=8, D=512. Output 256MB fp32 -> HBM-write-bound.
//
// R2: stage x + masks in smem once per block (coalesced, full MLP) so the
// inner loop has NO global loads -> loop is LDS(broadcast)+FFMA2+STG only.

#define B_DIM  8192
#define NF_DIM 128
#define G_DIM  16
#define F_DIM  8
#define D_DIM  512
#define TB     64    // b-values per block

// Flag: is masked_group_idx stored as int64 (1) or int32 (0)?
__device__ int g_is64;

__global__ void detect_idx_kernel(const int* __restrict__ mg) {
    // int64 data: high word == 0, low word in [0,16). int32 data: "high"
    // slot is a random group id, nonzero w.p. 15/16 each.
    int ok = 1;
    #pragma unroll 1
    for (int i = 0; i < 64; ++i) {
        int lo = mg[2 * i];
        int hi = mg[2 * i + 1];
        if (hi != 0 || ((unsigned)lo) >= 16u) { ok = 0; break; }
    }
    g_is64 = ok;
}

__device__ __forceinline__ unsigned long long fma2(unsigned long long a,
                                                   unsigned long long b,
                                                   unsigned long long c) {
    unsigned long long d;
    asm("fma.rn.f32x2 %0, %1, %2, %3;" : "=l"(d) : "l"(a), "l"(b), "l"(c));
    return d;
}

__device__ __forceinline__ unsigned long long pack2(float x) {
    unsigned long long r;
    asm("mov.b64 %0, {%1, %1};" : "=l"(r) : "r"(__float_as_uint(x)));
    return r;
}

union F4U {
    float4 v;
    struct { unsigned long long lo, hi; } u;
};

__global__ __launch_bounds__(128, 6) void ge_kernel(
    const float* __restrict__ x, const float* __restrict__ W,
    const float* __restrict__ bias, const int* __restrict__ mg,
    float* __restrict__ out)
{
    __shared__ float4 sx[TB * 2];   // x[b0+t, g*8 .. g*8+8) as 2 float4 per t
    __shared__ int    smask[TB];

    const int g  = blockIdx.y;
    const int d4 = threadIdx.x;            // 0..127, owns out[.., g, 4*d4 .. 4*d4+3]
    const int b0 = blockIdx.x * TB;

    // ---- Stage x tile: 128 threads, one float4 each (full MLP, one-time). ----
    {
        const int row  = threadIdx.x >> 1;          // 0..63
        const int half = threadIdx.x & 1;           // 0..1
        sx[threadIdx.x] = *reinterpret_cast<const float4*>(
            x + (size_t)(b0 + row) * NF_DIM + g * F_DIM + half * 4);
    }
    // ---- Stage masks. ----
    if (threadIdx.x < TB) {
        const int b = b0 + threadIdx.x;
        smask[threadIdx.x] = g_is64 ? mg[2 * b] : mg[b];
    }

    // ---- Preload W[g, :, 4*d4 .. 4*d4+3] (8 x float4 = 32 regs) + bias. ----
    F4U w[F_DIM];
    #pragma unroll
    for (int f = 0; f < F_DIM; ++f)
        w[f].v = *reinterpret_cast<const float4*>(
            W + (size_t)(g * F_DIM + f) * D_DIM + d4 * 4);
    F4U bb;
    bb.v = *reinterpret_cast<const float4*>(bias + (size_t)g * D_DIM + d4 * 4);

    __syncthreads();

    float4* outp = reinterpret_cast<float4*>(
        out + ((size_t)b0 * G_DIM + g) * D_DIM) + d4;
    const int ostride = G_DIM * D_DIM / 4;          // float4 stride per b

    #pragma unroll 2
    for (int t = 0; t < TB; ++t) {
        const float4 xa = sx[2 * t];
        const float4 xb = sx[2 * t + 1];
        const int    m  = smask[t];

        F4U acc;
        acc.u.lo = bb.u.lo;
        acc.u.hi = bb.u.hi;
        const float xf[F_DIM] = {xa.x, xa.y, xa.z, xa.w, xb.x, xb.y, xb.z, xb.w};
        #pragma unroll
        for (int f = 0; f < F_DIM; ++f) {
            unsigned long long xs = pack2(xf[f]);
            acc.u.lo = fma2(xs, w[f].u.lo, acc.u.lo);   // d pair (0,1)
            acc.u.hi = fma2(xs, w[f].u.hi, acc.u.hi);   // d pair (2,3)
        }

        if (m == g) acc.v = make_float4(0.f, 0.f, 0.f, 0.f);

        // Streaming store: output (256MB) is write-once, don't thrash L2.
        __stcs(outp + (size_t)t * ostride, acc.v);
    }
}

extern "C" void kernel_launch(void* const* d_in, const int* in_sizes, int n_in,
                              void* d_out, int out_size) {
    const float* x    = (const float*)d_in[0];
    const float* W    = (const float*)d_in[1];
    const float* bias = (const float*)d_in[2];
    // d_in[3] = group_idx: identity arange(G*F).reshape(G,F) -> ignored.
    const int*   mg   = (const int*)d_in[4];
    float*       out  = (float*)d_out;

    detect_idx_kernel<<<1, 1>>>(mg);

    dim3 grid(B_DIM / TB, G_DIM);
    ge_kernel<<<grid, 128>>>(x, W, bias, mg, out);
}

// round 3
// speedup vs baseline: 1.1215x; 1.0441x over previous
#include <cuda_runtime.h>

// GroupEmbedding: out[b,g,d] = sum_f x[b, g*8+f] * W[g,f,d] + bias[g,d],
// zeroed where masked_group_idx[b] == g.
// B=8192, NF=128, G=16, F=8, D=512. Output 256MB fp32 -> HBM-write-bound.
//
// R3: single kernel (per-block mask-dtype vote on first 128 ints), 256 thr/blk
// with d-pair ownership -> ~50 regs -> 5 blocks/SM (62.5% occ) to keep the
// DRAM write queues full (R2 showed DRAM only 58% active = concurrency gap).

#define B_DIM  8192
#define NF_DIM 128
#define G_DIM  16
#define F_DIM  8
#define D_DIM  512
#define TB     64    // b-values per block
#define TPB    256

__device__ __forceinline__ unsigned long long fma2(unsigned long long a,
                                                   unsigned long long b,
                                                   unsigned long long c) {
    unsigned long long d;
    asm("fma.rn.f32x2 %0, %1, %2, %3;" : "=l"(d) : "l"(a), "l"(b), "l"(c));
    return d;
}

__device__ __forceinline__ unsigned long long pack2(float x) {
    unsigned long long r;
    asm("mov.b64 %0, {%1, %1};" : "=l"(r) : "r"(__float_as_uint(x)));
    return r;
}

union U2 {
    float2 v;
    unsigned long long u;
};

__global__ __launch_bounds__(TPB, 5) void ge_kernel(
    const float* __restrict__ x, const float* __restrict__ W,
    const float* __restrict__ bias, const int* __restrict__ mg,
    float* __restrict__ out)
{
    __shared__ float4 sx[TB * 2];   // x[b0+t, g*8 .. g*8+8) as 2 float4 per t
    __shared__ int    smask[TB];
    __shared__ int    sflag;        // 1 if masked_group_idx is int64

    const int g  = blockIdx.y;
    const int b0 = blockIdx.x * TB;
    const int d2 = threadIdx.x;     // 0..255, owns out[.., g, 2*d2, 2*d2+1]

    if (threadIdx.x == 0) sflag = 1;
    __syncthreads();

    // ---- Mask-dtype vote on the FIRST 128 ints (safe for both layouts;
    //      identical data for every block -> consistent decision; L2-hot).
    //      int64 data: hi word 0, lo in [0,16). int32: "hi" slot is a random
    //      group id, nonzero w.p. 15/16 per slot -> FP prob ~16^-64.
    if (threadIdx.x < 64) {
        int2 p = reinterpret_cast<const int2*>(mg)[threadIdx.x];
        if (p.y != 0 || ((unsigned)p.x) >= 16u) sflag = 0;  // benign race: all write 0
    }

    // ---- Stage x tile: threads 0..127, one float4 each (full MLP). ----
    if (threadIdx.x < 128) {
        const int row  = threadIdx.x >> 1;
        const int half = threadIdx.x & 1;
        sx[threadIdx.x] = *reinterpret_cast<const float4*>(
            x + (size_t)(b0 + row) * NF_DIM + g * F_DIM + half * 4);
    }

    // ---- Preload W[g, :, 2*d2 .. 2*d2+1] (8 x float2 = 16 regs) + bias. ----
    U2 w[F_DIM];
    #pragma unroll
    for (int f = 0; f < F_DIM; ++f)
        w[f].v = *reinterpret_cast<const float2*>(
            W + (size_t)(g * F_DIM + f) * D_DIM + d2 * 2);
    U2 bb;
    bb.v = *reinterpret_cast<const float2*>(bias + (size_t)g * D_DIM + d2 * 2);

    __syncthreads();                 // sflag + sx visible

    // ---- Stage masks (needs sflag). ----
    if (threadIdx.x < TB) {
        const int b = b0 + threadIdx.x;
        smask[threadIdx.x] = sflag ? mg[2 * b] : mg[b];
    }
    __syncthreads();

    float2* outp = reinterpret_cast<float2*>(
        out + ((size_t)b0 * G_DIM + g) * D_DIM) + d2;
    const int ostride = G_DIM * D_DIM / 2;   // float2 stride per b

    #pragma unroll 2
    for (int t = 0; t < TB; ++t) {
        const float4 xa = sx[2 * t];
        const float4 xb = sx[2 * t + 1];
        const int    m  = smask[t];

        U2 acc;
        acc.u = bb.u;
        const float xf[F_DIM] = {xa.x, xa.y, xa.z, xa.w, xb.x, xb.y, xb.z, xb.w};
        #pragma unroll
        for (int f = 0; f < F_DIM; ++f)
            acc.u = fma2(pack2(xf[f]), w[f].u, acc.u);

        if (m == g) acc.v = make_float2(0.f, 0.f);

        // Streaming store: output (256MB) is write-once, don't thrash L2.
        __stcs(outp + (size_t)t * ostride, acc.v);
    }
}

extern "C" void kernel_launch(void* const* d_in, const int* in_sizes, int n_in,
                              void* d_out, int out_size) {
    const float* x    = (const float*)d_in[0];
    const float* W    = (const float*)d_in[1];
    const float* bias = (const float*)d_in[2];
    // d_in[3] = group_idx: identity arange(G*F).reshape(G,F) -> ignored.
    const int*   mg   = (const int*)d_in[4];
    float*       out  = (float*)d_out;

    dim3 grid(B_DIM / TB, G_DIM);
    ge_kernel<<<grid, TPB>>>(x, W, bias, mg, out);
}